// round 1
// baseline (speedup 1.0000x reference)
#include <cuda_runtime.h>
#include <cstdint>

#define BATCH 16
#define NCH   21
#define HH_   256
#define WW_   256
#define HW    65536
#define CHW   (NCH*HW)
#define DT    0.1f

// ---- scratch (allocation-free: __device__ globals) ----
__device__ float g_na[BATCH*HW];
__device__ float g_nb[BATCH*HW];
__device__ float g_nd[BATCH*HW];

__device__ __forceinline__ float lap12(const float v[9]) {
    return (v[0]+v[2]+v[6]+v[8] + 2.f*(v[1]+v[3]+v[5]+v[7]) - 12.f*v[4]) * (1.f/12.f);
}

// ============================================================
// Kernel A: oscillator substep -> scratch new_a/new_b/new_d
// (zero padding for conv_lap, +inf padding semantics for min pool)
// ============================================================
__global__ void osc_step(const float* __restrict__ x,
                         const float* __restrict__ sw, const float* __restrict__ sb,
                         const float* __restrict__ pAlpha, const float* __restrict__ pBeta,
                         const float* __restrict__ pOmega, const float* __restrict__ pK,
                         const float* __restrict__ pKappa) {
    int w = blockIdx.x * 128 + threadIdx.x;
    int h = blockIdx.y;
    int bb = blockIdx.z;
    int p = h * WW_ + w;
    const float* xb = x + (size_t)bb * CHW;

    const bool hu = (h > 0), hd = (h < HH_-1), wl = (w > 0), wr = (w < WW_-1);

    auto L9 = [&](const float* base, float v[9]) {
        const float* r0 = base + (h-1)*WW_;
        const float* r1 = base + h*WW_;
        const float* r2 = base + (h+1)*WW_;
        v[0] = (hu&&wl) ? r0[w-1] : 0.f;
        v[1] = hu       ? r0[w]   : 0.f;
        v[2] = (hu&&wr) ? r0[w+1] : 0.f;
        v[3] = wl       ? r1[w-1] : 0.f;
        v[4] =            r1[w];
        v[5] = wr       ? r1[w+1] : 0.f;
        v[6] = (hd&&wl) ? r2[w-1] : 0.f;
        v[7] = hd       ? r2[w]   : 0.f;
        v[8] = (hd&&wr) ? r2[w+1] : 0.f;
    };

    // channel 3 = alpha_ch
    float va[9];
    L9(xb + 3*HW, va);
    float eroded = va[4];
    if (hu) { eroded = fminf(eroded, va[1]); if (wl) eroded = fminf(eroded, va[0]); if (wr) eroded = fminf(eroded, va[2]); }
    if (wl) eroded = fminf(eroded, va[3]);
    if (wr) eroded = fminf(eroded, va[5]);
    if (hd) { eroded = fminf(eroded, va[7]); if (wl) eroded = fminf(eroded, va[6]); if (wr) eroded = fminf(eroded, va[8]); }
    float lapA = lap12(va);

    float q0 = va[4];
    float q1 = va[4] - eroded;
    float q2 = lapA;
    float q3 = xb[4*HW + p];
    float q4 = xb[5*HW + p];

    float I0 = sw[0]*q0 + sw[1]*q1 + sw[2]*q2 + sw[3]*q3 + sw[4]*q4 + sb[0];
    float I1 = sw[5]*q0 + sw[6]*q1 + sw[7]*q2 + sw[8]*q3 + sw[9]*q4 + sb[1];
    float I2 = sw[10]*q0 + sw[11]*q1 + sw[12]*q2 + sw[13]*q3 + sw[14]*q4 + sb[2];

    float vv[9];
    L9(xb + 15*HW, vv); float av = vv[4], lA = lap12(vv);
    L9(xb + 16*HW, vv); float bv = vv[4], lB = lap12(vv);
    L9(xb + 17*HW, vv); float dv = vv[4], lD = lap12(vv);

    float alpha = pAlpha[0], beta = pBeta[0], omega = pOmega[0], K = pK[0], kap = pKappa[0];

    float na = av + DT * (-alpha*av + omega*bv + K*lA + I0);
    float nb = bv + DT * (-alpha*bv - omega*av + K*lB + I1);
    float nd = dv + DT * (-beta*dv + kap*lD + I2);

    int gi = bb*HW + p;
    g_na[gi] = na; g_nb[gi] = nb; g_nd[gi] = nd;
}

// ============================================================
// Kernel B: avg_pool5 (zero pad) + normalize + correction,
// phase/amplitude, mod; writes out ch15..20 + phase + amplitude
// ============================================================
__global__ void osc_post(float* __restrict__ out,
                         const float* __restrict__ mw, const float* __restrict__ mb) {
    int w = blockIdx.x * 128 + threadIdx.x;
    int h = blockIdx.y;
    int bb = blockIdx.z;
    int p = h * WW_ + w;
    int gi = bb*HW + p;

    float sa = 0.f, sb2 = 0.f;
    #pragma unroll
    for (int dy = -2; dy <= 2; dy++) {
        int hh = h + dy;
        if (hh < 0 || hh >= HH_) continue;
        #pragma unroll
        for (int dx = -2; dx <= 2; dx++) {
            int ww = w + dx;
            if (ww < 0 || ww >= WW_) continue;
            int ii = bb*HW + hh*WW_ + ww;
            sa  += g_na[ii];
            sb2 += g_nb[ii];
        }
    }
    float aavg = sa * (1.f/25.f);
    float bavg = sb2 * (1.f/25.f);
    float rho = sqrtf(aavg*aavg + bavg*bavg + 1e-6f);
    aavg /= rho;
    bavg /= rho;

    float na = g_na[gi], nb = g_nb[gi], nd = g_nd[gi];
    float fa = na + DT * (aavg - na);
    float fb = nb + DT * (bavg - nb);

    float phase = sqrtf(fa*fa + fb*fb + 1e-6f);
    float amp = atan2f(fb, fa);

    float m0 = mw[0]*fa + mw[1]*fb + mw[2]*nd + mb[0];
    float m1 = mw[3]*fa + mw[4]*fb + mw[5]*nd + mb[1];
    float m2 = mw[6]*fa + mw[7]*fb + mw[8]*nd + mb[2];

    float* ob = out + (size_t)bb * CHW;
    ob[15*HW + p] = fa;
    ob[16*HW + p] = fb;
    ob[17*HW + p] = nd;
    ob[18*HW + p] = m0;
    ob[19*HW + p] = m1;
    ob[20*HW + p] = m2;

    float* phaseOut = out + (size_t)BATCH * CHW;
    float* ampOut   = phaseOut + (size_t)BATCH * HW;
    phaseOut[gi] = phase;
    ampOut[gi]   = amp;
}

// ============================================================
// Kernel C: perception (wrap) + MLP (packed f32x2) + gene update
// writes out ch0..14
// W1 is staged into shared in a permuted PACKED layout matching
// the per-channel generation order of the perception vector:
//   pair 2c   = (x_c,  sobelx_c)
//   pair 2c+1 = (sobely_c, lap_c)
// ============================================================
#define FMA2(acc, wv, pv) \
    asm("fma.rn.f32x2 %0, %1, %2, %0;" : "+l"(acc) : "l"(wv), "l"(pv))

__global__ __launch_bounds__(128) void gene_mlp(
    const float* __restrict__ x, const float* __restrict__ rn,
    const float* __restrict__ w1w, const float* __restrict__ w1b,
    const float* __restrict__ w2w, float* __restrict__ out) {

    __shared__ __align__(16) float sW1[96*84];
    __shared__ float4 sW2B[96];

    int tid = threadIdx.x;
    // stage W1 permuted+packed
    for (int idx = tid; idx < 96*84; idx += 128) {
        int hh = idx / 84;
        int r  = idx - hh*84;
        int i  = r >> 1;       // pair index 0..41
        int lane = r & 1;      // lo/hi within pair
        int c  = i >> 1;       // source channel 0..20
        int col;
        if ((i & 1) == 0) col = lane ? (21 + 3*c) : c;       // (x_c, sx_c)
        else              col = 22 + 3*c + lane;             // (sy_c, lap_c)
        sW1[idx] = w1w[hh*84 + col];
    }
    for (int hh = tid; hh < 96; hh += 128) {
        sW2B[hh] = make_float4(w2w[hh], w2w[96 + hh], w2w[192 + hh], w1b[hh]);
    }
    __syncthreads();

    int w  = blockIdx.x * 128 + tid;
    int bb = blockIdx.z;
    const float* xb = x + (size_t)bb * CHW;
    float* ob = out + (size_t)bb * CHW;

    // each block processes 4 rows to amortize the weight staging
    #pragma unroll 1
    for (int hy = 0; hy < 4; hy++) {
        int h = blockIdx.y * 4 + hy;
        int hm = (h - 1) & 255, hp = (h + 1) & 255;
        int wm = (w - 1) & 255, wp = (w + 1) & 255;
        int p = h * WW_ + w;

        unsigned long long p2[42];
        float g0 = 0.f, g1 = 0.f, g2 = 0.f, life = 0.f;

        #pragma unroll
        for (int c = 0; c < 21; c++) {
            const float* base = xb + c*HW;
            float n00 = base[hm*WW_ + wm], n01 = base[hm*WW_ + w], n02 = base[hm*WW_ + wp];
            float n10 = base[h*WW_ + wm],  n11 = base[p],          n12 = base[h*WW_ + wp];
            float n20 = base[hp*WW_ + wm], n21 = base[hp*WW_ + w], n22 = base[hp*WW_ + wp];
            float sx = (n02 - n00) + 2.f*(n12 - n10) + (n22 - n20);
            float sy = (n20 - n00) + 2.f*(n21 - n01) + (n22 - n02);
            float lp = n00 + n02 + n20 + n22 + 2.f*(n01 + n10 + n12 + n21) - 12.f*n11;
            asm("mov.b64 %0, {%1,%2};" : "=l"(p2[2*c])   : "f"(n11), "f"(sx));
            asm("mov.b64 %0, {%1,%2};" : "=l"(p2[2*c+1]) : "f"(sy),  "f"(lp));
            if (c < 12)  ob[c*HW + p] = n11;
            if (c == 12) g0 = n11;
            if (c == 13) g1 = n11;
            if (c == 14) g2 = n11;
            if (c == 3) {
                float mx = fmaxf(fmaxf(fmaxf(n00, n01), fmaxf(n02, n10)),
                                 fmaxf(fmaxf(n11, n12), fmaxf(fmaxf(n20, n21), n22)));
                life = (mx > 0.1f) ? 1.f : 0.f;
            }
        }

        float y0 = 0.f, y1 = 0.f, y2 = 0.f;
        #pragma unroll 2
        for (int hh = 0; hh < 96; hh++) {
            const ulonglong2* row = (const ulonglong2*)(sW1 + hh*84);
            unsigned long long a0 = 0ULL, a1 = 0ULL;
            #pragma unroll
            for (int i = 0; i < 21; i++) {
                ulonglong2 q = row[i];
                FMA2(a0, q.x, p2[2*i]);
                FMA2(a1, q.y, p2[2*i+1]);
            }
            float l0, h0, l1, h1;
            asm("mov.b64 {%0,%1}, %2;" : "=f"(l0), "=f"(h0) : "l"(a0));
            asm("mov.b64 {%0,%1}, %2;" : "=f"(l1), "=f"(h1) : "l"(a1));
            float4 wb = sW2B[hh];
            float hv = fmaxf((l0 + h0) + (l1 + h1) + wb.w, 0.f);
            y0 = fmaf(wb.x, hv, y0);
            y1 = fmaf(wb.y, hv, y1);
            y2 = fmaf(wb.z, hv, y2);
        }

        float mask = floorf(rn[(size_t)bb*HW + p] + 0.5f);
        float ml = mask * life;
        ob[12*HW + p] = g0 + y0 * ml;
        ob[13*HW + p] = g1 + y1 * ml;
        ob[14*HW + p] = g2 + y2 * ml;
    }
}

// ============================================================
extern "C" void kernel_launch(void* const* d_in, const int* in_sizes, int n_in,
                              void* d_out, int out_size) {
    const float* x     = (const float*)d_in[0];
    const float* rn    = (const float*)d_in[1];
    const float* w1w   = (const float*)d_in[2];
    const float* w1b   = (const float*)d_in[3];
    const float* w2w   = (const float*)d_in[4];
    const float* sloww = (const float*)d_in[5];
    const float* slowb = (const float*)d_in[6];
    const float* modw  = (const float*)d_in[7];
    const float* modb  = (const float*)d_in[8];
    const float* alpha = (const float*)d_in[9];
    const float* beta  = (const float*)d_in[10];
    const float* omega = (const float*)d_in[11];
    const float* K     = (const float*)d_in[12];
    const float* kappa = (const float*)d_in[13];
    float* out = (float*)d_out;

    dim3 blk(128, 1, 1);
    dim3 grd(WW_/128, HH_, BATCH);
    dim3 grd4(WW_/128, HH_/4, BATCH);

    osc_step<<<grd, blk>>>(x, sloww, slowb, alpha, beta, omega, K, kappa);
    osc_post<<<grd, blk>>>(out, modw, modb);
    gene_mlp<<<grd4, blk>>>(x, rn, w1w, w1b, w2w, out);
}

// round 3
// speedup vs baseline: 2.3044x; 2.3044x over previous
#include <cuda_runtime.h>
#include <cstdint>

#define BATCH 16
#define NCH   21
#define HH_   256
#define WW_   256
#define HW    65536
#define CHW   (NCH*HW)
#define DT    0.1f

// GEMM tiling
#define KT 11          // k8 tiles (K = 88 = 84 features + bias + 3 zero)
#define NT 12          // n8 tiles (N = 96 hidden)

// ---- scratch (allocation-free: __device__ globals) ----
__device__ float g_na[BATCH*HW];
__device__ float g_nb[BATCH*HW];
__device__ float g_nd[BATCH*HW];

__device__ __forceinline__ float lap12(const float v[9]) {
    return (v[0]+v[2]+v[6]+v[8] + 2.f*(v[1]+v[3]+v[5]+v[7]) - 12.f*v[4]) * (1.f/12.f);
}

// ============================================================
// Kernel A: oscillator substep -> scratch new_a/new_b/new_d
// ============================================================
__global__ void osc_step(const float* __restrict__ x,
                         const float* __restrict__ sw, const float* __restrict__ sb,
                         const float* __restrict__ pAlpha, const float* __restrict__ pBeta,
                         const float* __restrict__ pOmega, const float* __restrict__ pK,
                         const float* __restrict__ pKappa) {
    int w = blockIdx.x * 128 + threadIdx.x;
    int h = blockIdx.y;
    int bb = blockIdx.z;
    int p = h * WW_ + w;
    const float* xb = x + (size_t)bb * CHW;

    const bool hu = (h > 0), hd = (h < HH_-1), wl = (w > 0), wr = (w < WW_-1);

    auto L9 = [&](const float* base, float v[9]) {
        const float* r0 = base + (h-1)*WW_;
        const float* r1 = base + h*WW_;
        const float* r2 = base + (h+1)*WW_;
        v[0] = (hu&&wl) ? r0[w-1] : 0.f;
        v[1] = hu       ? r0[w]   : 0.f;
        v[2] = (hu&&wr) ? r0[w+1] : 0.f;
        v[3] = wl       ? r1[w-1] : 0.f;
        v[4] =            r1[w];
        v[5] = wr       ? r1[w+1] : 0.f;
        v[6] = (hd&&wl) ? r2[w-1] : 0.f;
        v[7] = hd       ? r2[w]   : 0.f;
        v[8] = (hd&&wr) ? r2[w+1] : 0.f;
    };

    float va[9];
    L9(xb + 3*HW, va);
    float eroded = va[4];
    if (hu) { eroded = fminf(eroded, va[1]); if (wl) eroded = fminf(eroded, va[0]); if (wr) eroded = fminf(eroded, va[2]); }
    if (wl) eroded = fminf(eroded, va[3]);
    if (wr) eroded = fminf(eroded, va[5]);
    if (hd) { eroded = fminf(eroded, va[7]); if (wl) eroded = fminf(eroded, va[6]); if (wr) eroded = fminf(eroded, va[8]); }
    float lapA = lap12(va);

    float q0 = va[4];
    float q1 = va[4] - eroded;
    float q2 = lapA;
    float q3 = xb[4*HW + p];
    float q4 = xb[5*HW + p];

    float I0 = sw[0]*q0 + sw[1]*q1 + sw[2]*q2 + sw[3]*q3 + sw[4]*q4 + sb[0];
    float I1 = sw[5]*q0 + sw[6]*q1 + sw[7]*q2 + sw[8]*q3 + sw[9]*q4 + sb[1];
    float I2 = sw[10]*q0 + sw[11]*q1 + sw[12]*q2 + sw[13]*q3 + sw[14]*q4 + sb[2];

    float vv[9];
    L9(xb + 15*HW, vv); float av = vv[4], lA = lap12(vv);
    L9(xb + 16*HW, vv); float bv = vv[4], lB = lap12(vv);
    L9(xb + 17*HW, vv); float dv = vv[4], lD = lap12(vv);

    float alpha = pAlpha[0], beta = pBeta[0], omega = pOmega[0], K = pK[0], kap = pKappa[0];

    float na = av + DT * (-alpha*av + omega*bv + K*lA + I0);
    float nb = bv + DT * (-alpha*bv - omega*av + K*lB + I1);
    float nd = dv + DT * (-beta*dv + kap*lD + I2);

    int gi = bb*HW + p;
    g_na[gi] = na; g_nb[gi] = nb; g_nd[gi] = nd;
}

// ============================================================
// Kernel B: avg_pool5 + normalize + correction + phase/amp/mod
// ============================================================
__global__ void osc_post(float* __restrict__ out,
                         const float* __restrict__ mw, const float* __restrict__ mb) {
    int w = blockIdx.x * 128 + threadIdx.x;
    int h = blockIdx.y;
    int bb = blockIdx.z;
    int p = h * WW_ + w;
    int gi = bb*HW + p;

    float sa = 0.f, sb2 = 0.f;
    #pragma unroll
    for (int dy = -2; dy <= 2; dy++) {
        int hh = h + dy;
        if (hh < 0 || hh >= HH_) continue;
        #pragma unroll
        for (int dx = -2; dx <= 2; dx++) {
            int ww = w + dx;
            if (ww < 0 || ww >= WW_) continue;
            int ii = bb*HW + hh*WW_ + ww;
            sa  += g_na[ii];
            sb2 += g_nb[ii];
        }
    }
    float aavg = sa * (1.f/25.f);
    float bavg = sb2 * (1.f/25.f);
    float rho = sqrtf(aavg*aavg + bavg*bavg + 1e-6f);
    aavg /= rho;
    bavg /= rho;

    float na = g_na[gi], nb = g_nb[gi], nd = g_nd[gi];
    float fa = na + DT * (aavg - na);
    float fb = nb + DT * (bavg - nb);

    float phase = sqrtf(fa*fa + fb*fb + 1e-6f);
    float amp = atan2f(fb, fa);

    float m0 = mw[0]*fa + mw[1]*fb + mw[2]*nd + mb[0];
    float m1 = mw[3]*fa + mw[4]*fb + mw[5]*nd + mb[1];
    float m2 = mw[6]*fa + mw[7]*fb + mw[8]*nd + mb[2];

    float* ob = out + (size_t)bb * CHW;
    ob[15*HW + p] = fa;
    ob[16*HW + p] = fb;
    ob[17*HW + p] = nd;
    ob[18*HW + p] = m0;
    ob[19*HW + p] = m1;
    ob[20*HW + p] = m2;

    float* phaseOut = out + (size_t)BATCH * CHW;
    float* ampOut   = phaseOut + (size_t)BATCH * HW;
    phaseOut[gi] = phase;
    ampOut[gi]   = amp;
}

// ============================================================
// Kernel C: perception (wrap) + warp mma.sync tf32 MLP + gene update
// M = pixels (32/warp), N = 96 hidden, K = 88 (84 + bias + pad)
// ============================================================
__device__ __forceinline__ uint32_t tf32c(float x) {
    uint32_t r;
    asm("cvt.rna.tf32.f32 %0, %1;" : "=r"(r) : "f"(x));
    return r;
}

#define MMA_TF32(c0,c1,c2,c3, a0,a1,a2,a3, b0,b1) \
    asm volatile("mma.sync.aligned.m16n8k8.row.col.f32.tf32.tf32.f32 " \
        "{%0,%1,%2,%3}, {%4,%5,%6,%7}, {%8,%9}, {%0,%1,%2,%3};" \
        : "+f"(c0), "+f"(c1), "+f"(c2), "+f"(c3) \
        : "r"(a0), "r"(a1), "r"(a2), "r"(a3), "r"(b0), "r"(b1))

// dynamic SMEM layout (bytes)
#define SM_BFRAG 0                       // NT*KT*32 u64 = 33792
#define SM_W2    33792                   // 96 float4 = 1536
#define SM_YBUF  35328                   // 128 float4 = 2048
#define SM_A     37888                   // 128 rows x 512B (chunk-swizzled)
#define SM_TOTAL (SM_A + 128*512)        // 103424

// A tile addressing: row r in [0,128), chunk c in [0,22) of 16B; word j in [0,4)
__device__ __forceinline__ char* a_addr(char* smem, int r, int c, int j) {
    return smem + SM_A + r*512 + ((c ^ (r & 7)) << 4) + (j << 2);
}

__global__ void __launch_bounds__(128) gene_mlp_mma(
    const float* __restrict__ x, const float* __restrict__ rn,
    const float* __restrict__ w1w, const float* __restrict__ w1b,
    const float* __restrict__ w2w, float* __restrict__ out) {

    extern __shared__ __align__(512) char smem[];
    unsigned long long* bfrag = reinterpret_cast<unsigned long long*>(smem + SM_BFRAG);
    float4* w2s  = reinterpret_cast<float4*>(smem + SM_W2);
    float4* ybuf = reinterpret_cast<float4*>(smem + SM_YBUF);

    const int tid  = threadIdx.x;
    const int lane = tid & 31;
    const int warp = tid >> 5;
    const int w4   = lane >> 2;   // 0..7
    const int c4   = lane & 3;    // 0..3

    // ---- stage B fragments (once): B[k_row][n_col] = W1^T with bias row 84 ----
    // feature r -> w1 column: r = 4c+j, j==0 -> c (x), else 21+3c+(j-1) (sx,sy,lap)
    for (int i = tid; i < NT*KT*32; i += 128) {
        int n   = i / (KT*32);
        int rem = i - n*(KT*32);
        int k   = rem >> 5;
        int l   = rem & 31;
        int col = 8*n + (l >> 2);
        int r0  = 8*k + (l & 3);
        int r1  = r0 + 4;
        float b0f = 0.f, b1f = 0.f;
        if (r0 < 84) { int cc = r0 >> 2, j = r0 & 3; b0f = w1w[col*84 + (j == 0 ? cc : 21 + 3*cc + (j-1))]; }
        else if (r0 == 84) b0f = w1b[col];
        if (r1 < 84) { int cc = r1 >> 2, j = r1 & 3; b1f = w1w[col*84 + (j == 0 ? cc : 21 + 3*cc + (j-1))]; }
        else if (r1 == 84) b1f = w1b[col];
        unsigned long long pk = (unsigned long long)tf32c(b0f) |
                                ((unsigned long long)tf32c(b1f) << 32);
        bfrag[i] = pk;
    }
    for (int n = tid; n < 96; n += 128)
        w2s[n] = make_float4(w2w[n], w2w[96 + n], w2w[192 + n], 0.f);

    // bias column (feature 84 -> chunk 21, word 0) = 1.0; words 85..87 zero
    *reinterpret_cast<float4*>(a_addr(smem, tid, 21, 0)) = make_float4(1.f, 0.f, 0.f, 0.f);
    __syncthreads();

    const int w  = blockIdx.x * 128 + tid;
    const int bb = blockIdx.z;
    const float* xb = x + (size_t)bb * CHW;
    float* ob = out + (size_t)bb * CHW;

    #pragma unroll 1
    for (int t = 0; t < 4; t++) {
        const int h  = blockIdx.y * 4 + t;
        const int hm = (h - 1) & 255, hp = (h + 1) & 255;
        const int wm = (w - 1) & 255, wp = (w + 1) & 255;
        const int p  = h * WW_ + w;

        float g0 = 0.f, g1 = 0.f, g2 = 0.f, life = 0.f;

        __syncwarp();
        // ---- perception -> A row (row = tid), chunk c per channel ----
        #pragma unroll
        for (int c = 0; c < 21; c++) {
            const float* base = xb + c*HW;
            float n00 = base[hm*WW_ + wm], n01 = base[hm*WW_ + w], n02 = base[hm*WW_ + wp];
            float n10 = base[h*WW_ + wm],  n11 = base[p],          n12 = base[h*WW_ + wp];
            float n20 = base[hp*WW_ + wm], n21 = base[hp*WW_ + w], n22 = base[hp*WW_ + wp];
            float sx = (n02 - n00) + 2.f*(n12 - n10) + (n22 - n20);
            float sy = (n20 - n00) + 2.f*(n21 - n01) + (n22 - n02);
            float lp = n00 + n02 + n20 + n22 + 2.f*(n01 + n10 + n12 + n21) - 12.f*n11;
            *reinterpret_cast<float4*>(a_addr(smem, tid, c, 0)) = make_float4(n11, sx, sy, lp);
            if (c < 12)  ob[c*HW + p] = n11;
            if (c == 12) g0 = n11;
            if (c == 13) g1 = n11;
            if (c == 14) g2 = n11;
            if (c == 3) {
                float mx = fmaxf(fmaxf(fmaxf(n00, n01), fmaxf(n02, n10)),
                                 fmaxf(fmaxf(n11, n12), fmaxf(fmaxf(n20, n21), n22)));
                life = (mx > 0.1f) ? 1.f : 0.f;
            }
        }
        __syncwarp();

        // ---- preload A fragments: afr[m][k][0..3] ----
        uint32_t afr[2][KT][4];
        #pragma unroll
        for (int m = 0; m < 2; m++) {
            int r0 = warp*32 + m*16 + w4;
            int r1 = r0 + 8;
            #pragma unroll
            for (int k = 0; k < KT; k++) {
                afr[m][k][0] = *reinterpret_cast<uint32_t*>(a_addr(smem, r0, 2*k,     c4));
                afr[m][k][1] = *reinterpret_cast<uint32_t*>(a_addr(smem, r1, 2*k,     c4));
                afr[m][k][2] = *reinterpret_cast<uint32_t*>(a_addr(smem, r0, 2*k + 1, c4));
                afr[m][k][3] = *reinterpret_cast<uint32_t*>(a_addr(smem, r1, 2*k + 1, c4));
            }
        }

        // ---- GEMM + fused epilogue over n-tiles ----
        float yv[2][2][3];
        #pragma unroll
        for (int m = 0; m < 2; m++)
            #pragma unroll
            for (int rh = 0; rh < 2; rh++)
                yv[m][rh][0] = yv[m][rh][1] = yv[m][rh][2] = 0.f;

        #pragma unroll
        for (int n = 0; n < NT; n++) {
            float c00=0.f,c01=0.f,c02=0.f,c03=0.f;
            float c10=0.f,c11=0.f,c12=0.f,c13=0.f;
            const unsigned long long* bp = bfrag + n*(KT*32) + lane;
            #pragma unroll
            for (int k = 0; k < KT; k++) {
                unsigned long long bv = bp[k*32];
                uint32_t b0 = (uint32_t)bv, b1 = (uint32_t)(bv >> 32);
                MMA_TF32(c00,c01,c02,c03, afr[0][k][0],afr[0][k][1],afr[0][k][2],afr[0][k][3], b0,b1);
                MMA_TF32(c10,c11,c12,c13, afr[1][k][0],afr[1][k][1],afr[1][k][2],afr[1][k][3], b0,b1);
            }
            int n0 = 8*n + 2*c4;
            float4 wA = w2s[n0], wB = w2s[n0 + 1];
            c00 = fmaxf(c00, 0.f); c01 = fmaxf(c01, 0.f);
            c02 = fmaxf(c02, 0.f); c03 = fmaxf(c03, 0.f);
            c10 = fmaxf(c10, 0.f); c11 = fmaxf(c11, 0.f);
            c12 = fmaxf(c12, 0.f); c13 = fmaxf(c13, 0.f);
            yv[0][0][0] += wA.x*c00 + wB.x*c01;  yv[0][0][1] += wA.y*c00 + wB.y*c01;  yv[0][0][2] += wA.z*c00 + wB.z*c01;
            yv[0][1][0] += wA.x*c02 + wB.x*c03;  yv[0][1][1] += wA.y*c02 + wB.y*c03;  yv[0][1][2] += wA.z*c02 + wB.z*c03;
            yv[1][0][0] += wA.x*c10 + wB.x*c11;  yv[1][0][1] += wA.y*c10 + wB.y*c11;  yv[1][0][2] += wA.z*c10 + wB.z*c11;
            yv[1][1][0] += wA.x*c12 + wB.x*c13;  yv[1][1][1] += wA.y*c12 + wB.y*c13;  yv[1][1][2] += wA.z*c12 + wB.z*c13;
        }

        // quad reduce (lanes sharing lane>>2)
        #pragma unroll
        for (int m = 0; m < 2; m++)
            #pragma unroll
            for (int rh = 0; rh < 2; rh++)
                #pragma unroll
                for (int j = 0; j < 3; j++) {
                    float v = yv[m][rh][j];
                    v += __shfl_xor_sync(0xFFFFFFFFu, v, 1);
                    v += __shfl_xor_sync(0xFFFFFFFFu, v, 2);
                    yv[m][rh][j] = v;
                }
        if (c4 == 0) {
            #pragma unroll
            for (int m = 0; m < 2; m++) {
                ybuf[warp*32 + m*16 + w4]     = make_float4(yv[m][0][0], yv[m][0][1], yv[m][0][2], 0.f);
                ybuf[warp*32 + m*16 + w4 + 8] = make_float4(yv[m][1][0], yv[m][1][1], yv[m][1][2], 0.f);
            }
        }
        __syncwarp();
        float4 yo = ybuf[tid];

        float mask = floorf(rn[(size_t)bb*HW + p] + 0.5f);
        float ml = mask * life;
        ob[12*HW + p] = g0 + yo.x * ml;
        ob[13*HW + p] = g1 + yo.y * ml;
        ob[14*HW + p] = g2 + yo.z * ml;
    }
}

// ============================================================
extern "C" void kernel_launch(void* const* d_in, const int* in_sizes, int n_in,
                              void* d_out, int out_size) {
    const float* x     = (const float*)d_in[0];
    const float* rn    = (const float*)d_in[1];
    const float* w1w   = (const float*)d_in[2];
    const float* w1b   = (const float*)d_in[3];
    const float* w2w   = (const float*)d_in[4];
    const float* sloww = (const float*)d_in[5];
    const float* slowb = (const float*)d_in[6];
    const float* modw  = (const float*)d_in[7];
    const float* modb  = (const float*)d_in[8];
    const float* alpha = (const float*)d_in[9];
    const float* beta  = (const float*)d_in[10];
    const float* omega = (const float*)d_in[11];
    const float* K     = (const float*)d_in[12];
    const float* kappa = (const float*)d_in[13];
    float* out = (float*)d_out;

    static int smemSet = 0;
    if (!smemSet) {
        cudaFuncSetAttribute(gene_mlp_mma, cudaFuncAttributeMaxDynamicSharedMemorySize, SM_TOTAL);
        smemSet = 1;
    }

    dim3 blk(128, 1, 1);
    dim3 grd(WW_/128, HH_, BATCH);
    dim3 grdG(WW_/128, HH_/4, BATCH);

    osc_step<<<grd, blk>>>(x, sloww, slowb, alpha, beta, omega, K, kappa);
    osc_post<<<grd, blk>>>(out, modw, modb);
    gene_mlp_mma<<<grdG, blk, SM_TOTAL>>>(x, rn, w1w, w1b, w2w, out);
}